// round 13
// baseline (speedup 1.0000x reference)
#include <cuda_runtime.h>
#include <cuda_fp16.h>
#include <cstdint>

// ---------------------------------------------------------------------------
#define T_STEPS 1024
#define BATCH   256
#define FDIM    512
#define MROWS   (T_STEPS * BATCH)      // 262144
#define BF      (BATCH * FDIM)         // 131072

// GEMM tiling: CTA 128m x 128n, KC=64, 8 warps (4m x 2n), warp 32m x 64n.
// A = bit-packed spikes (1 bit/elem), whole 512-k strip in 10 KB smem,
//     expanded to fp16 in registers by ALU.
// B = 2 fp16 planes, double-buffered, swizzle + ldmatrix (verified path).
#define MT      128
#define NT      128
#define KC      64
#define NCHUNK  (FDIM / KC)            // 8
#define NPLANE  2
#define ABIT_STRIDE 80                 // bytes per row: 64 B bits + 16 pad
#define ABIT_SZ (MT * ABIT_STRIDE)     // 10240 B
#define B_STG   (NPLANE * NT * 128)    // 32768 B
#define SMEM_TOTAL (ABIT_SZ + 2 * B_STG)   // 75776 B -> 2 CTAs/SM

// Device scratch (static arrays are the sanctioned scratch mechanism)
__device__ uint32_t g_Sbit[(size_t)MROWS * 16];        // 16 MB, 512 bits/row
__device__ uint16_t g_Wp[NPLANE * FDIM * FDIM];        // fp16 planes hi/lo
__device__ float    g_xs[(size_t)MROWS * FDIM];        // fc outputs (512 MB)

// ---------------------------------------------------------------------------
__device__ __forceinline__ uint32_t smem_u32(const void* p) {
    uint32_t a;
    asm("{ .reg .u64 t; cvta.to.shared.u64 t, %1; cvt.u32.u64 %0, t; }"
        : "=r"(a) : "l"(p));
    return a;
}
__device__ __forceinline__ void cp16(uint32_t dst, const void* src) {
    asm volatile("cp.async.cg.shared.global [%0], [%1], 16;"
                 :: "r"(dst), "l"(src) : "memory");
}
// 2-bit spike pair -> fp16x2 {lo=bit0, hi=bit1}, exact 0.0/1.0 halves.
__device__ __forceinline__ uint32_t expand2(uint32_t v2) {
    return (v2 & 1u) * 0x3C00u | (v2 & 2u) * 0x1E000000u;
}
#define LDSM4(r0, r1, r2, r3, addr)                                        \
    asm volatile("ldmatrix.sync.aligned.m8n8.x4.shared.b16 "               \
                 "{%0,%1,%2,%3}, [%4];"                                    \
                 : "=r"(r0), "=r"(r1), "=r"(r2), "=r"(r3) : "r"(addr))

#define HMMA(c, a, b0_, b1_)                                               \
    asm volatile("mma.sync.aligned.m16n8k16.row.col.f32.f16.f16.f32 "      \
                 "{%0,%1,%2,%3}, {%4,%5,%6,%7}, {%8,%9}, {%0,%1,%2,%3};"   \
                 : "+f"((c)[0]), "+f"((c)[1]), "+f"((c)[2]), "+f"((c)[3])  \
                 : "r"((a)[0]), "r"((a)[1]), "r"((a)[2]), "r"((a)[3]),     \
                   "r"(b0_), "r"(b1_))

// ---------------------------------------------------------------------------
// Kernel 1: exact 2-way fp16 split of W.
// ---------------------------------------------------------------------------
__global__ void wsplit_kernel(const float* __restrict__ W) {
    int idx = blockIdx.x * 256 + threadIdx.x;       // 262144 = 512*512
    float w = W[idx];
    __half wh = __float2half_rn(w);
    float r1 = w - __half2float(wh);                // exact in fp32
    __half wl = __float2half_rn(r1);
    g_Wp[idx]               = *(const uint16_t*)&wh;
    g_Wp[FDIM * FDIM + idx] = *(const uint16_t*)&wl;
}

// ---------------------------------------------------------------------------
// Kernel 2: pack spikes to bits. One warp per row; word j bit k = col j*32+k.
// ---------------------------------------------------------------------------
__global__ void pack_kernel(const float* __restrict__ spk) {
    const int row = blockIdx.x * 8 + (threadIdx.x >> 5);
    const int lane = threadIdx.x & 31;
    const float* p = spk + (size_t)row * FDIM;
    uint32_t myword = 0;
    #pragma unroll
    for (int it = 0; it < 16; it++) {
        float x = p[it * 32 + lane];
        uint32_t b = __ballot_sync(0xFFFFFFFFu, x != 0.0f);
        if (lane == it) myword = b;
    }
    if (lane < 16) g_Sbit[(size_t)row * 16 + lane] = myword;
}

// ---------------------------------------------------------------------------
// Kernel 3: fp16 HMMA GEMM for ONE n-quarter (n0 passed by value).
// Core is byte-identical to the verified R12 mainloop.
// ---------------------------------------------------------------------------
__global__ void __launch_bounds__(256, 2)
gemm_kernel(int n0) {
    extern __shared__ char smem[];
    const uint32_t sb = smem_u32(smem);
    const int tid = threadIdx.x;
    const int l = tid & 31, wid = tid >> 5;
    const int wm = wid & 3, wn = wid >> 2;          // 4 m-warps x 2 n-warps
    const size_t m0 = (size_t)blockIdx.y * MT;

    float acc[2][8][4];                              // [mt][nt][frag] = 64 regs
    #pragma unroll
    for (int mt = 0; mt < 2; mt++)
        #pragma unroll
        for (int nt = 0; nt < 8; nt++)
            #pragma unroll
            for (int j = 0; j < 4; j++) acc[mt][nt][j] = 0.0f;

    // ---- A bits: whole 128-row x 512-bit strip, one group ----
    {
        #pragma unroll
        for (int q = 0; q < 2; q++) {                // 512 cp16
            int u = q * 256 + tid;
            int row = u >> 2, seg = u & 3;
            cp16(sb + row * ABIT_STRIDE + seg * 16,
                 g_Sbit + (m0 + row) * 16 + seg * 4);
        }
        asm volatile("cp.async.commit_group;" ::: "memory");
    }
    // ---- B loader: 2 planes x 128 rows x 128 B fp16, swizzled ----
    auto load_B = [&](int c, int stg) {
        const uint32_t base = sb + ABIT_SZ + stg * B_STG;
        #pragma unroll
        for (int q = 0; q < 8; q++) {                // 2048 cp16
            int u = q * 256 + tid;
            int pl = u >> 10, rem = u & 1023;
            int row = rem >> 3, seg = rem & 7;
            cp16(base + pl * (NT * 128) + row * 128
                      + ((seg * 16) ^ ((row & 7) << 4)),
                 g_Wp + (size_t)pl * (FDIM * FDIM)
                      + (size_t)(n0 + row) * FDIM + c * KC + seg * 8);
        }
        asm volatile("cp.async.commit_group;" ::: "memory");
    };

    load_B(0, 0);
    load_B(1, 1);

    // per-lane address components
    const int lq = l >> 2;                            // lane quarter 0..7
    const int sh0 = 2 * (l & 3);                      // bit offset in 16-col blk
    const int qB = l >> 3;
    const int rBl = ((qB >> 1) << 3) + (l & 7);       // B row within 16-pair
    const int cB = (qB & 1) * 16;
    const uint32_t bswz = ((uint32_t)(rBl & 7)) << 4;
    const uint32_t abit0 = sb + (uint32_t)((wm * 32 + lq) * ABIT_STRIDE);

    #pragma unroll 1
    for (int c = 0; c < NCHUNK; c++) {
        if (c < NCHUNK - 1) asm volatile("cp.async.wait_group 1;" ::: "memory");
        else                asm volatile("cp.async.wait_group 0;" ::: "memory");
        __syncthreads();

        // Load this chunk's 64 bits for each of the lane's 4 rows.
        uint32_t w0[2][2], w1[2][2];                 // [mt][half] -> lo/hi word
        #pragma unroll
        for (int mt = 0; mt < 2; mt++)
            #pragma unroll
            for (int h = 0; h < 2; h++) {
                uint32_t ad = abit0 + (uint32_t)((mt * 16 + h * 8) * ABIT_STRIDE
                                                 + c * 8);
                asm volatile("ld.shared.v2.b32 {%0,%1}, [%2];"
                             : "=r"(w0[mt][h]), "=r"(w1[mt][h]) : "r"(ad));
            }

        const uint32_t bbase = sb + ABIT_SZ + (c & 1) * B_STG;

        #pragma unroll
        for (int ks = 0; ks < 4; ks++) {
            const int shift = (ks & 1) * 16 + sh0;
            uint32_t a[2][4];
            #pragma unroll
            for (int mt = 0; mt < 2; mt++) {
                uint32_t vlo0 = ((ks < 2 ? w0[mt][0] : w1[mt][0]) >> shift) & 0x303u;
                uint32_t vlo1 = ((ks < 2 ? w0[mt][1] : w1[mt][1]) >> shift) & 0x303u;
                a[mt][0] = expand2(vlo0 & 3u);        // row r,   cols c,c+1
                a[mt][1] = expand2(vlo1 & 3u);        // row r+8, cols c,c+1
                a[mt][2] = expand2((vlo0 >> 8) & 3u); // row r,   cols c+8,c+9
                a[mt][3] = expand2((vlo1 >> 8) & 3u); // row r+8, cols c+8,c+9
            }
            #pragma unroll
            for (int pl = 0; pl < NPLANE; pl++) {
                #pragma unroll
                for (int p2 = 0; p2 < 4; p2++) {     // 2 n-tiles per ldmatrix
                    uint32_t bd = bbase + pl * (NT * 128)
                                + (wn * 64 + p2 * 16 + rBl) * 128
                                + (((uint32_t)(ks * 32 + cB)) ^ bswz);
                    uint32_t b0, b1, b2, b3;
                    LDSM4(b0, b1, b2, b3, bd);
                    #pragma unroll
                    for (int mt = 0; mt < 2; mt++) {
                        HMMA(acc[mt][2 * p2],     a[mt], b0, b1);
                        HMMA(acc[mt][2 * p2 + 1], a[mt], b2, b3);
                    }
                }
            }
        }

        __syncthreads();                 // B stage (c&1) consumed
        if (c + 2 < NCHUNK) load_B(c + 2, c & 1);
    }

    // ---- epilogue: direct coalesced float2 stores ----
    #pragma unroll
    for (int mt = 0; mt < 2; mt++)
        #pragma unroll
        for (int nt = 0; nt < 8; nt++) {
            const size_t row = m0 + wm * 32 + mt * 16 + (l >> 2);
            const int    col = n0 + wn * 64 + nt * 8 + (l & 3) * 2;
            *(float2*)(g_xs + row * FDIM + col) =
                make_float2(acc[mt][nt][0], acc[mt][nt][1]);
            *(float2*)(g_xs + (row + 8) * FDIM + col) =
                make_float2(acc[mt][nt][2], acc[mt][nt][3]);
        }
}

// ---------------------------------------------------------------------------
// Kernel 4: LIF scan for one 128-column f-quarter (overlaps later GEMMs).
// fp32-exact in reference op order; 16-deep load batch, streaming loads.
// ---------------------------------------------------------------------------
__global__ void __launch_bounds__(256)
scan_kernel(float* __restrict__ out, int f0) {
    const int idx = blockIdx.x * 256 + threadIdx.x;   // 0..32767
    const int b = idx >> 7;
    const int bf = b * FDIM + f0 + (idx & 127);
    const float* p = g_xs + bf;
    float v = 0.0f, i = 0.0f, z = 0.0f;

    for (int t = 0; t < T_STEPS; t += 16) {
        float x[16];
        #pragma unroll
        for (int u = 0; u < 16; u++)
            x[u] = __ldcs(p + (size_t)(t + u) * BF);
        #pragma unroll
        for (int u = 0; u < 16; u++) {
            float vd = __fadd_rn(v, __fmul_rn(0.1f, __fadd_rn(-v, i)));
            float id = __fadd_rn(i, -__fmul_rn(0.2f, i));
            bool s = vd > 1.0f;
            z = s ? 1.0f : 0.0f;
            v = s ? 0.0f : vd;
            i = __fadd_rn(id, x[u]);
        }
    }
    out[bf]          = z;
    out[BF + bf]     = v;
    out[2 * BF + bf] = i;
}

// ---------------------------------------------------------------------------
extern "C" void kernel_launch(void* const* d_in, const int* in_sizes, int n_in,
                              void* d_out, int out_size) {
    const float* spikes = (const float*)d_in[0];  // [T, B, F] fp32 (binary)
    const float* W      = (const float*)d_in[1];  // [F, F] fp32
    float* out          = (float*)d_out;          // [3, B, F] fp32
    (void)in_sizes; (void)n_in; (void)out_size;

    // One-time host-side resources (no device memory; identical work per call)
    static bool inited = false;
    static cudaStream_t s2;
    static cudaEvent_t evG[4], evJ;
    if (!inited) {
        cudaStreamCreateWithFlags(&s2, cudaStreamNonBlocking);
        for (int q = 0; q < 4; q++)
            cudaEventCreateWithFlags(&evG[q], cudaEventDisableTiming);
        cudaEventCreateWithFlags(&evJ, cudaEventDisableTiming);
        cudaFuncSetAttribute(gemm_kernel,
                             cudaFuncAttributeMaxDynamicSharedMemorySize,
                             SMEM_TOTAL);
        inited = true;
    }

    wsplit_kernel<<<(FDIM * FDIM) / 256, 256>>>(W);
    pack_kernel<<<MROWS / 8, 256>>>(spikes);

    // GEMM n-quarters on the main stream; each quarter's scan forks to s2
    // and overlaps the remaining GEMM quarters.
    for (int q = 0; q < 4; q++) {
        gemm_kernel<<<dim3(1, MROWS / MT), 256, SMEM_TOTAL>>>(q * NT);
        cudaEventRecord(evG[q], 0);
        cudaStreamWaitEvent(s2, evG[q], 0);
        scan_kernel<<<(BATCH * NT) / 256, 256, 0, s2>>>(out, q * NT);
    }
    cudaEventRecord(evJ, s2);
    cudaStreamWaitEvent(0, evJ, 0);     // join fork before returning
}

// round 14
// speedup vs baseline: 1.0530x; 1.0530x over previous
#include <cuda_runtime.h>
#include <cuda_fp16.h>
#include <cstdint>

// ---------------------------------------------------------------------------
#define T_STEPS 1024
#define BATCH   256
#define FDIM    512
#define MROWS   (T_STEPS * BATCH)      // 262144
#define BF      (BATCH * FDIM)         // 131072

// GEMM tiling: CTA 128m x 128n, KC=64, 8 warps as 2m x 4n, warp 64m x 32n.
// (2m x 4n halves redundant cross-warp B fragment loads vs 4m x 2n: smem
// crossbar 288 -> 192 KB per chunk per SM, below the HMMA floor.)
// A = bit-packed spikes, whole 512-k strip in 10 KB smem, ALU-expanded.
// B = 2 fp16 planes, double-buffered, swizzle + ldmatrix (verified path).
#define MT      128
#define NT      128
#define KC      64
#define NCHUNK  (FDIM / KC)            // 8
#define NPLANE  2
#define ABIT_STRIDE 80                 // bytes per row: 64 B bits + 16 pad
#define ABIT_SZ (MT * ABIT_STRIDE)     // 10240 B
#define B_STG   (NPLANE * NT * 128)    // 32768 B
#define SMEM_TOTAL (ABIT_SZ + 2 * B_STG)   // 75776 B -> 2 CTAs/SM

// Device scratch (static arrays are the sanctioned scratch mechanism)
__device__ uint32_t g_Sbit[(size_t)MROWS * 16];        // 16 MB, 512 bits/row
__device__ uint16_t g_Wp[NPLANE * FDIM * FDIM];        // fp16 planes hi/lo
__device__ float    g_xs[(size_t)MROWS * FDIM];        // fc outputs (512 MB)

// ---------------------------------------------------------------------------
__device__ __forceinline__ uint32_t smem_u32(const void* p) {
    uint32_t a;
    asm("{ .reg .u64 t; cvta.to.shared.u64 t, %1; cvt.u32.u64 %0, t; }"
        : "=r"(a) : "l"(p));
    return a;
}
__device__ __forceinline__ void cp16(uint32_t dst, const void* src) {
    asm volatile("cp.async.cg.shared.global [%0], [%1], 16;"
                 :: "r"(dst), "l"(src) : "memory");
}
// bits 0,1 of t -> fp16x2 {lo=bit0, hi=bit1}; exact 0.0/1.0 halves.
__device__ __forceinline__ uint32_t expand_lo(uint32_t t) {
    return (t & 1u) * 0x3C00u | (t & 2u) * 0x1E000000u;
}
// bits 8,9 of t -> fp16x2 {lo=bit8, hi=bit9}
__device__ __forceinline__ uint32_t expand_hi(uint32_t t) {
    return (t & 0x100u) * 0x3Cu | (t & 0x200u) * 0x1E0000u;
}
#define LDSM4(r0, r1, r2, r3, addr)                                        \
    asm volatile("ldmatrix.sync.aligned.m8n8.x4.shared.b16 "               \
                 "{%0,%1,%2,%3}, [%4];"                                    \
                 : "=r"(r0), "=r"(r1), "=r"(r2), "=r"(r3) : "r"(addr))

#define HMMA(c, a, b0_, b1_)                                               \
    asm volatile("mma.sync.aligned.m16n8k16.row.col.f32.f16.f16.f32 "      \
                 "{%0,%1,%2,%3}, {%4,%5,%6,%7}, {%8,%9}, {%0,%1,%2,%3};"   \
                 : "+f"((c)[0]), "+f"((c)[1]), "+f"((c)[2]), "+f"((c)[3])  \
                 : "r"((a)[0]), "r"((a)[1]), "r"((a)[2]), "r"((a)[3]),     \
                   "r"(b0_), "r"(b1_))

// ---------------------------------------------------------------------------
// Kernel 1: exact 2-way fp16 split of W.
// ---------------------------------------------------------------------------
__global__ void wsplit_kernel(const float* __restrict__ W) {
    int idx = blockIdx.x * 256 + threadIdx.x;       // 262144 = 512*512
    float w = W[idx];
    __half wh = __float2half_rn(w);
    float r1 = w - __half2float(wh);                // exact in fp32
    __half wl = __float2half_rn(r1);
    g_Wp[idx]               = *(const uint16_t*)&wh;
    g_Wp[FDIM * FDIM + idx] = *(const uint16_t*)&wl;
}

// ---------------------------------------------------------------------------
// Kernel 2: pack spikes to bits. One warp per row; word j bit k = col j*32+k.
// ---------------------------------------------------------------------------
__global__ void pack_kernel(const float* __restrict__ spk) {
    const int row = blockIdx.x * 8 + (threadIdx.x >> 5);
    const int lane = threadIdx.x & 31;
    const float* p = spk + (size_t)row * FDIM;
    uint32_t myword = 0;
    #pragma unroll
    for (int it = 0; it < 16; it++) {
        float x = p[it * 32 + lane];
        uint32_t b = __ballot_sync(0xFFFFFFFFu, x != 0.0f);
        if (lane == it) myword = b;
    }
    if (lane < 16) g_Sbit[(size_t)row * 16 + lane] = myword;
}

// ---------------------------------------------------------------------------
// Kernel 3: fp16 HMMA GEMM  xs[M,512] = sum_p S @ Wp^T   (fp32 accum)
// ---------------------------------------------------------------------------
__global__ void __launch_bounds__(256, 2)
gemm_kernel() {
    extern __shared__ char smem[];
    const uint32_t sb = smem_u32(smem);
    const int tid = threadIdx.x;
    const int l = tid & 31, wid = tid >> 5;
    const int wm = wid & 1, wn = wid >> 1;          // 2 m-warps x 4 n-warps
    const int n0 = blockIdx.x * NT;
    const size_t m0 = (size_t)blockIdx.y * MT;

    float acc[4][4][4];                              // [mt][nt][frag] = 64 regs
    #pragma unroll
    for (int mt = 0; mt < 4; mt++)
        #pragma unroll
        for (int nt = 0; nt < 4; nt++)
            #pragma unroll
            for (int j = 0; j < 4; j++) acc[mt][nt][j] = 0.0f;

    // ---- A bits: whole 128-row x 512-bit strip, one group ----
    {
        #pragma unroll
        for (int q = 0; q < 2; q++) {                // 512 cp16
            int u = q * 256 + tid;
            int row = u >> 2, seg = u & 3;
            cp16(sb + row * ABIT_STRIDE + seg * 16,
                 g_Sbit + (m0 + row) * 16 + seg * 4);
        }
        asm volatile("cp.async.commit_group;" ::: "memory");
    }
    // ---- B loader: 2 planes x 128 rows x 128 B fp16, swizzled ----
    auto load_B = [&](int c, int stg) {
        const uint32_t base = sb + ABIT_SZ + stg * B_STG;
        #pragma unroll
        for (int q = 0; q < 8; q++) {                // 2048 cp16
            int u = q * 256 + tid;
            int pl = u >> 10, rem = u & 1023;
            int row = rem >> 3, seg = rem & 7;
            cp16(base + pl * (NT * 128) + row * 128
                      + ((seg * 16) ^ ((row & 7) << 4)),
                 g_Wp + (size_t)pl * (FDIM * FDIM)
                      + (size_t)(n0 + row) * FDIM + c * KC + seg * 8);
        }
        asm volatile("cp.async.commit_group;" ::: "memory");
    };

    load_B(0, 0);
    load_B(1, 1);

    // per-lane address components
    const int lq = l >> 2;                            // lane quarter 0..7
    const int sh0 = 2 * (l & 3);                      // bit offset in 16-col blk
    const int qB = l >> 3;
    const int rBl = ((qB >> 1) << 3) + (l & 7);       // B row within 16-pair
    const int cB = (qB & 1) * 16;
    const uint32_t bswz = ((uint32_t)(rBl & 7)) << 4;
    const uint32_t abit0 = sb + (uint32_t)((wm * 64 + lq) * ABIT_STRIDE);

    #pragma unroll 1
    for (int c = 0; c < NCHUNK; c++) {
        if (c < NCHUNK - 1) asm volatile("cp.async.wait_group 1;" ::: "memory");
        else                asm volatile("cp.async.wait_group 0;" ::: "memory");
        __syncthreads();

        // Load this chunk's 64 bits for each of the lane's 8 rows,
        // pre-shifted by the lane's column offset.
        uint32_t w0[4][2], w1[4][2];                 // [mt][half] -> lo/hi word
        #pragma unroll
        for (int mt = 0; mt < 4; mt++)
            #pragma unroll
            for (int h = 0; h < 2; h++) {
                uint32_t ad = abit0 + (uint32_t)((mt * 16 + h * 8) * ABIT_STRIDE
                                                 + c * 8);
                asm volatile("ld.shared.v2.b32 {%0,%1}, [%2];"
                             : "=r"(w0[mt][h]), "=r"(w1[mt][h]) : "r"(ad));
                w0[mt][h] >>= sh0;
                w1[mt][h] >>= sh0;
            }

        const uint32_t bbase = sb + ABIT_SZ + (c & 1) * B_STG;

        #pragma unroll
        for (int ks = 0; ks < 4; ks++) {
            const int shift = (ks & 1) * 16;
            uint32_t a[4][4];
            #pragma unroll
            for (int mt = 0; mt < 4; mt++) {
                uint32_t t0 = (ks < 2 ? w0[mt][0] : w1[mt][0]) >> shift;
                uint32_t t1 = (ks < 2 ? w0[mt][1] : w1[mt][1]) >> shift;
                a[mt][0] = expand_lo(t0);            // row r,   cols c,c+1
                a[mt][1] = expand_lo(t1);            // row r+8, cols c,c+1
                a[mt][2] = expand_hi(t0);            // row r,   cols c+8,c+9
                a[mt][3] = expand_hi(t1);            // row r+8, cols c+8,c+9
            }
            #pragma unroll
            for (int pl = 0; pl < NPLANE; pl++) {
                #pragma unroll
                for (int p2 = 0; p2 < 2; p2++) {     // 2 n-tiles per ldmatrix
                    uint32_t bd = bbase + pl * (NT * 128)
                                + (wn * 32 + p2 * 16 + rBl) * 128
                                + (((uint32_t)(ks * 32 + cB)) ^ bswz);
                    uint32_t b0, b1, b2, b3;
                    LDSM4(b0, b1, b2, b3, bd);
                    #pragma unroll
                    for (int mt = 0; mt < 4; mt++) {
                        HMMA(acc[mt][2 * p2],     a[mt], b0, b1);
                        HMMA(acc[mt][2 * p2 + 1], a[mt], b2, b3);
                    }
                }
            }
        }

        __syncthreads();                 // B stage (c&1) consumed
        if (c + 2 < NCHUNK) load_B(c + 2, c & 1);
    }

    // ---- epilogue: direct coalesced float2 stores ----
    #pragma unroll
    for (int mt = 0; mt < 4; mt++)
        #pragma unroll
        for (int nt = 0; nt < 4; nt++) {
            const size_t row = m0 + wm * 64 + mt * 16 + (l >> 2);
            const int    col = n0 + wn * 32 + nt * 8 + (l & 3) * 2;
            *(float2*)(g_xs + row * FDIM + col) =
                make_float2(acc[mt][nt][0], acc[mt][nt][1]);
            *(float2*)(g_xs + (row + 8) * FDIM + col) =
                make_float2(acc[mt][nt][2], acc[mt][nt][3]);
        }
}

// ---------------------------------------------------------------------------
// Kernel 4: LIF scan. Thread = one neuron (b,f); xs[t][bf] coalesced.
// fp32-exact in reference op order; 16-deep load batch, streaming loads.
// ---------------------------------------------------------------------------
__global__ void __launch_bounds__(256)
scan_kernel(float* __restrict__ out) {
    const int bf = blockIdx.x * 256 + threadIdx.x;
    const float* p = g_xs + bf;
    float v = 0.0f, i = 0.0f, z = 0.0f;

    for (int t = 0; t < T_STEPS; t += 16) {
        float x[16];
        #pragma unroll
        for (int u = 0; u < 16; u++)
            x[u] = __ldcs(p + (size_t)(t + u) * BF);
        #pragma unroll
        for (int u = 0; u < 16; u++) {
            float vd = __fadd_rn(v, __fmul_rn(0.1f, __fadd_rn(-v, i)));
            float id = __fadd_rn(i, -__fmul_rn(0.2f, i));
            bool s = vd > 1.0f;
            z = s ? 1.0f : 0.0f;
            v = s ? 0.0f : vd;
            i = __fadd_rn(id, x[u]);
        }
    }
    out[bf]          = z;
    out[BF + bf]     = v;
    out[2 * BF + bf] = i;
}

// ---------------------------------------------------------------------------
extern "C" void kernel_launch(void* const* d_in, const int* in_sizes, int n_in,
                              void* d_out, int out_size) {
    const float* spikes = (const float*)d_in[0];  // [T, B, F] fp32 (binary)
    const float* W      = (const float*)d_in[1];  // [F, F] fp32
    float* out          = (float*)d_out;          // [3, B, F] fp32
    (void)in_sizes; (void)n_in; (void)out_size;

    cudaFuncSetAttribute(gemm_kernel,
                         cudaFuncAttributeMaxDynamicSharedMemorySize, SMEM_TOTAL);

    wsplit_kernel<<<(FDIM * FDIM) / 256, 256>>>(W);
    pack_kernel<<<MROWS / 8, 256>>>(spikes);
    gemm_kernel<<<dim3(FDIM / NT, MROWS / MT), 256, SMEM_TOTAL>>>();
    scan_kernel<<<BF / 256, 256>>>(out);
}

// round 15
// speedup vs baseline: 1.1263x; 1.0696x over previous
#include <cuda_runtime.h>
#include <cuda_fp16.h>
#include <cstdint>

// ---------------------------------------------------------------------------
#define T_STEPS 1024
#define BATCH   256
#define FDIM    512
#define MROWS   (T_STEPS * BATCH)      // 262144
#define BF      (BATCH * FDIM)         // 131072

// GEMM tiling: CTA 128m x 128n, KC=64, 8 warps (4m x 2n), warp 32m x 64n.
// A = bit-packed spikes (1 bit/elem), whole 512-k strip in 10 KB smem,
//     expanded to fp16 in registers by ALU (R12-verified layout).
// B = 2 fp16 planes, 3-stage cp.async ring, swizzle + ldmatrix.
// Single barrier per chunk; refill issue overlapped with MMA.
#define MT      128
#define NT      128
#define KC      64
#define NCHUNK  (FDIM / KC)            // 8
#define NPLANE  2
#define NSTAGE  3
#define ABIT_STRIDE 80                 // bytes per row: 64 B bits + 16 pad
#define ABIT_SZ (MT * ABIT_STRIDE)     // 10240 B
#define B_STG   (NPLANE * NT * 128)    // 32768 B
#define SMEM_TOTAL (ABIT_SZ + NSTAGE * B_STG)  // 108544 B -> 2 CTAs/SM

// Device scratch (static arrays are the sanctioned scratch mechanism)
__device__ uint32_t g_Sbit[(size_t)MROWS * 16];        // 16 MB, 512 bits/row
__device__ uint16_t g_Wp[NPLANE * FDIM * FDIM];        // fp16 planes hi/lo
__device__ float    g_xs[(size_t)MROWS * FDIM];        // fc outputs (512 MB)

// ---------------------------------------------------------------------------
__device__ __forceinline__ uint32_t smem_u32(const void* p) {
    uint32_t a;
    asm("{ .reg .u64 t; cvta.to.shared.u64 t, %1; cvt.u32.u64 %0, t; }"
        : "=r"(a) : "l"(p));
    return a;
}
__device__ __forceinline__ void cp16(uint32_t dst, const void* src) {
    asm volatile("cp.async.cg.shared.global [%0], [%1], 16;"
                 :: "r"(dst), "l"(src) : "memory");
}
// 2-bit spike pair -> fp16x2 {lo=bit0, hi=bit1}, exact 0.0/1.0 halves.
__device__ __forceinline__ uint32_t expand2(uint32_t v2) {
    return (v2 & 1u) * 0x3C00u | (v2 & 2u) * 0x1E000000u;
}
#define LDSM4(r0, r1, r2, r3, addr)                                        \
    asm volatile("ldmatrix.sync.aligned.m8n8.x4.shared.b16 "               \
                 "{%0,%1,%2,%3}, [%4];"                                    \
                 : "=r"(r0), "=r"(r1), "=r"(r2), "=r"(r3) : "r"(addr))

#define HMMA(c, a, b0_, b1_)                                               \
    asm volatile("mma.sync.aligned.m16n8k16.row.col.f32.f16.f16.f32 "      \
                 "{%0,%1,%2,%3}, {%4,%5,%6,%7}, {%8,%9}, {%0,%1,%2,%3};"   \
                 : "+f"((c)[0]), "+f"((c)[1]), "+f"((c)[2]), "+f"((c)[3])  \
                 : "r"((a)[0]), "r"((a)[1]), "r"((a)[2]), "r"((a)[3]),     \
                   "r"(b0_), "r"(b1_))

// ---------------------------------------------------------------------------
// Kernel 1: exact 2-way fp16 split of W.
// ---------------------------------------------------------------------------
__global__ void wsplit_kernel(const float* __restrict__ W) {
    int idx = blockIdx.x * 256 + threadIdx.x;       // 262144 = 512*512
    float w = W[idx];
    __half wh = __float2half_rn(w);
    float r1 = w - __half2float(wh);                // exact in fp32
    __half wl = __float2half_rn(r1);
    g_Wp[idx]               = *(const uint16_t*)&wh;
    g_Wp[FDIM * FDIM + idx] = *(const uint16_t*)&wl;
}

// ---------------------------------------------------------------------------
// Kernel 2: pack spikes to bits. One warp per row; word j bit k = col j*32+k.
// ---------------------------------------------------------------------------
__global__ void pack_kernel(const float* __restrict__ spk) {
    const int row = blockIdx.x * 8 + (threadIdx.x >> 5);
    const int lane = threadIdx.x & 31;
    const float* p = spk + (size_t)row * FDIM;
    uint32_t myword = 0;
    #pragma unroll
    for (int it = 0; it < 16; it++) {
        float x = p[it * 32 + lane];
        uint32_t b = __ballot_sync(0xFFFFFFFFu, x != 0.0f);
        if (lane == it) myword = b;
    }
    if (lane < 16) g_Sbit[(size_t)row * 16 + lane] = myword;
}

// ---------------------------------------------------------------------------
// Kernel 3: fp16 HMMA GEMM  xs[M,512] = sum_p S @ Wp^T   (fp32 accum)
// R12 core; 3-stage B ring, one barrier per chunk. Slot (c+2)%3 was consumed
// by chunk c-1; the top-of-iteration barrier proves all warps finished c-1,
// so refilling it before compute(c) is race-free and overlaps with MMAs.
// ---------------------------------------------------------------------------
__global__ void __launch_bounds__(256, 2)
gemm_kernel() {
    extern __shared__ char smem[];
    const uint32_t sb = smem_u32(smem);
    const int tid = threadIdx.x;
    const int l = tid & 31, wid = tid >> 5;
    const int wm = wid & 3, wn = wid >> 2;          // 4 m-warps x 2 n-warps
    const int n0 = blockIdx.x * NT;
    const size_t m0 = (size_t)blockIdx.y * MT;

    float acc[2][8][4];                              // [mt][nt][frag] = 64 regs
    #pragma unroll
    for (int mt = 0; mt < 2; mt++)
        #pragma unroll
        for (int nt = 0; nt < 8; nt++)
            #pragma unroll
            for (int j = 0; j < 4; j++) acc[mt][nt][j] = 0.0f;

    // ---- A bits: whole 128-row x 512-bit strip, one group (oldest) ----
    {
        #pragma unroll
        for (int q = 0; q < 2; q++) {                // 512 cp16
            int u = q * 256 + tid;
            int row = u >> 2, seg = u & 3;
            cp16(sb + row * ABIT_STRIDE + seg * 16,
                 g_Sbit + (m0 + row) * 16 + seg * 4);
        }
        asm volatile("cp.async.commit_group;" ::: "memory");
    }
    // ---- B loader: 2 planes x 128 rows x 128 B fp16, swizzled ----
    auto load_B = [&](int c, int stg) {
        const uint32_t base = sb + ABIT_SZ + stg * B_STG;
        #pragma unroll
        for (int q = 0; q < 8; q++) {                // 2048 cp16
            int u = q * 256 + tid;
            int pl = u >> 10, rem = u & 1023;
            int row = rem >> 3, seg = rem & 7;
            cp16(base + pl * (NT * 128) + row * 128
                      + ((seg * 16) ^ ((row & 7) << 4)),
                 g_Wp + (size_t)pl * (FDIM * FDIM)
                      + (size_t)(n0 + row) * FDIM + c * KC + seg * 8);
        }
        asm volatile("cp.async.commit_group;" ::: "memory");
    };

    load_B(0, 0);
    load_B(1, 1);

    // per-lane address components
    const int lq = l >> 2;                            // lane quarter 0..7
    const int sh0 = 2 * (l & 3);                      // bit offset in 16-col blk
    const int qB = l >> 3;
    const int rBl = ((qB >> 1) << 3) + (l & 7);       // B row within 16-pair
    const int cB = (qB & 1) * 16;
    const uint32_t bswz = ((uint32_t)(rBl & 7)) << 4;
    const uint32_t abit0 = sb + (uint32_t)((wm * 32 + lq) * ABIT_STRIDE);

    #pragma unroll 1
    for (int c = 0; c < NCHUNK; c++) {
        // Pending commit groups at this point: {B(c), B(c+1)} (+A if c==0,
        // which is older than both). wait 1 -> B(c) and A complete.
        if (c < NCHUNK - 1) asm volatile("cp.async.wait_group 1;" ::: "memory");
        else                asm volatile("cp.async.wait_group 0;" ::: "memory");
        __syncthreads();                 // all warps finished chunk c-1

        if (c + 2 < NCHUNK)              // refill slot (c+2)%3 == (c-1)%3
            load_B(c + 2, (c + 2) % NSTAGE);

        // Load this chunk's 64 bits for each of the lane's 4 rows.
        uint32_t w0[2][2], w1[2][2];                 // [mt][half] -> lo/hi word
        #pragma unroll
        for (int mt = 0; mt < 2; mt++)
            #pragma unroll
            for (int h = 0; h < 2; h++) {
                uint32_t ad = abit0 + (uint32_t)((mt * 16 + h * 8) * ABIT_STRIDE
                                                 + c * 8);
                asm volatile("ld.shared.v2.b32 {%0,%1}, [%2];"
                             : "=r"(w0[mt][h]), "=r"(w1[mt][h]) : "r"(ad));
            }

        const uint32_t bbase = sb + ABIT_SZ + (c % NSTAGE) * B_STG;

        #pragma unroll
        for (int ks = 0; ks < 4; ks++) {
            const int shift = (ks & 1) * 16 + sh0;
            uint32_t a[2][4];
            #pragma unroll
            for (int mt = 0; mt < 2; mt++) {
                uint32_t vlo0 = ((ks < 2 ? w0[mt][0] : w1[mt][0]) >> shift) & 0x303u;
                uint32_t vlo1 = ((ks < 2 ? w0[mt][1] : w1[mt][1]) >> shift) & 0x303u;
                a[mt][0] = expand2(vlo0 & 3u);        // row r,   cols c,c+1
                a[mt][1] = expand2(vlo1 & 3u);        // row r+8, cols c,c+1
                a[mt][2] = expand2((vlo0 >> 8) & 3u); // row r,   cols c+8,c+9
                a[mt][3] = expand2((vlo1 >> 8) & 3u); // row r+8, cols c+8,c+9
            }
            #pragma unroll
            for (int pl = 0; pl < NPLANE; pl++) {
                #pragma unroll
                for (int p2 = 0; p2 < 4; p2++) {     // 2 n-tiles per ldmatrix
                    uint32_t bd = bbase + pl * (NT * 128)
                                + (wn * 64 + p2 * 16 + rBl) * 128
                                + (((uint32_t)(ks * 32 + cB)) ^ bswz);
                    uint32_t b0, b1, b2, b3;
                    LDSM4(b0, b1, b2, b3, bd);
                    #pragma unroll
                    for (int mt = 0; mt < 2; mt++) {
                        HMMA(acc[mt][2 * p2],     a[mt], b0, b1);
                        HMMA(acc[mt][2 * p2 + 1], a[mt], b2, b3);
                    }
                }
            }
        }
    }

    // ---- epilogue: direct coalesced float2 stores ----
    #pragma unroll
    for (int mt = 0; mt < 2; mt++)
        #pragma unroll
        for (int nt = 0; nt < 8; nt++) {
            const size_t row = m0 + wm * 32 + mt * 16 + (l >> 2);
            const int    col = n0 + wn * 64 + nt * 8 + (l & 3) * 2;
            *(float2*)(g_xs + row * FDIM + col) =
                make_float2(acc[mt][nt][0], acc[mt][nt][1]);
            *(float2*)(g_xs + (row + 8) * FDIM + col) =
                make_float2(acc[mt][nt][2], acc[mt][nt][3]);
        }
}

// ---------------------------------------------------------------------------
// Kernel 4: LIF scan. Thread = one neuron (b,f); xs[t][bf] coalesced.
// fp32-exact in reference op order; 16-deep load batch, streaming loads.
// ---------------------------------------------------------------------------
__global__ void __launch_bounds__(256)
scan_kernel(float* __restrict__ out) {
    const int bf = blockIdx.x * 256 + threadIdx.x;
    const float* p = g_xs + bf;
    float v = 0.0f, i = 0.0f, z = 0.0f;

    for (int t = 0; t < T_STEPS; t += 16) {
        float x[16];
        #pragma unroll
        for (int u = 0; u < 16; u++)
            x[u] = __ldcs(p + (size_t)(t + u) * BF);
        #pragma unroll
        for (int u = 0; u < 16; u++) {
            float vd = __fadd_rn(v, __fmul_rn(0.1f, __fadd_rn(-v, i)));
            float id = __fadd_rn(i, -__fmul_rn(0.2f, i));
            bool s = vd > 1.0f;
            z = s ? 1.0f : 0.0f;
            v = s ? 0.0f : vd;
            i = __fadd_rn(id, x[u]);
        }
    }
    out[bf]          = z;
    out[BF + bf]     = v;
    out[2 * BF + bf] = i;
}

// ---------------------------------------------------------------------------
extern "C" void kernel_launch(void* const* d_in, const int* in_sizes, int n_in,
                              void* d_out, int out_size) {
    const float* spikes = (const float*)d_in[0];  // [T, B, F] fp32 (binary)
    const float* W      = (const float*)d_in[1];  // [F, F] fp32
    float* out          = (float*)d_out;          // [3, B, F] fp32
    (void)in_sizes; (void)n_in; (void)out_size;

    cudaFuncSetAttribute(gemm_kernel,
                         cudaFuncAttributeMaxDynamicSharedMemorySize, SMEM_TOTAL);

    wsplit_kernel<<<(FDIM * FDIM) / 256, 256>>>(W);
    pack_kernel<<<MROWS / 8, 256>>>(spikes);
    gemm_kernel<<<dim3(FDIM / NT, MROWS / MT), 256, SMEM_TOTAL>>>();
    scan_kernel<<<BF / 256, 256>>>(out);
}

// round 16
// speedup vs baseline: 1.1566x; 1.0269x over previous
#include <cuda_runtime.h>
#include <cuda_fp16.h>
#include <cstdint>

// ---------------------------------------------------------------------------
#define T_STEPS 1024
#define BATCH   256
#define FDIM    512
#define MROWS   (T_STEPS * BATCH)      // 262144
#define BF      (BATCH * FDIM)         // 131072
#define NPIPE   4                      // m-chunks for pack/gemm pipelining
#define MCHUNK  (MROWS / NPIPE)        // 65536 rows per chunk

// GEMM tiling (R12-verified best): CTA 128m x 128n, KC=64, 8 warps (4m x 2n).
// A = bit-packed spikes, whole 512-k strip in 10 KB smem, ALU-expanded.
// B = 2 fp16 planes, double-buffered, swizzle + ldmatrix.
#define MT      128
#define NT      128
#define KC      64
#define NCHUNK  (FDIM / KC)            // 8
#define NPLANE  2
#define ABIT_STRIDE 80                 // bytes per row: 64 B bits + 16 pad
#define ABIT_SZ (MT * ABIT_STRIDE)     // 10240 B
#define B_STG   (NPLANE * NT * 128)    // 32768 B
#define SMEM_TOTAL (ABIT_SZ + 2 * B_STG)   // 75776 B -> 2 CTAs/SM

// Device scratch (static arrays are the sanctioned scratch mechanism)
__device__ uint32_t g_Sbit[(size_t)MROWS * 16];        // 16 MB, 512 bits/row
__device__ uint16_t g_Wp[NPLANE * FDIM * FDIM];        // fp16 planes hi/lo
__device__ float    g_xs[(size_t)MROWS * FDIM];        // fc outputs (512 MB)

// ---------------------------------------------------------------------------
__device__ __forceinline__ uint32_t smem_u32(const void* p) {
    uint32_t a;
    asm("{ .reg .u64 t; cvta.to.shared.u64 t, %1; cvt.u32.u64 %0, t; }"
        : "=r"(a) : "l"(p));
    return a;
}
__device__ __forceinline__ void cp16(uint32_t dst, const void* src) {
    asm volatile("cp.async.cg.shared.global [%0], [%1], 16;"
                 :: "r"(dst), "l"(src) : "memory");
}
// 2-bit spike pair -> fp16x2 {lo=bit0, hi=bit1}, exact 0.0/1.0 halves.
__device__ __forceinline__ uint32_t expand2(uint32_t v2) {
    return (v2 & 1u) * 0x3C00u | (v2 & 2u) * 0x1E000000u;
}
#define LDSM4(r0, r1, r2, r3, addr)                                        \
    asm volatile("ldmatrix.sync.aligned.m8n8.x4.shared.b16 "               \
                 "{%0,%1,%2,%3}, [%4];"                                    \
                 : "=r"(r0), "=r"(r1), "=r"(r2), "=r"(r3) : "r"(addr))

#define HMMA(c, a, b0_, b1_)                                               \
    asm volatile("mma.sync.aligned.m16n8k16.row.col.f32.f16.f16.f32 "      \
                 "{%0,%1,%2,%3}, {%4,%5,%6,%7}, {%8,%9}, {%0,%1,%2,%3};"   \
                 : "+f"((c)[0]), "+f"((c)[1]), "+f"((c)[2]), "+f"((c)[3])  \
                 : "r"((a)[0]), "r"((a)[1]), "r"((a)[2]), "r"((a)[3]),     \
                   "r"(b0_), "r"(b1_))

// ---------------------------------------------------------------------------
// Kernel 1: exact 2-way fp16 split of W.
// ---------------------------------------------------------------------------
__global__ void wsplit_kernel(const float* __restrict__ W) {
    int idx = blockIdx.x * 256 + threadIdx.x;       // 262144 = 512*512
    float w = W[idx];
    __half wh = __float2half_rn(w);
    float r1 = w - __half2float(wh);                // exact in fp32
    __half wl = __float2half_rn(r1);
    g_Wp[idx]               = *(const uint16_t*)&wh;
    g_Wp[FDIM * FDIM + idx] = *(const uint16_t*)&wl;
}

// ---------------------------------------------------------------------------
// Kernel 2: pack spikes to bits for an m-chunk. One warp per row.
// ---------------------------------------------------------------------------
__global__ void pack_kernel(const float* __restrict__ spk, int r_off) {
    const int row = r_off + blockIdx.x * 8 + (threadIdx.x >> 5);
    const int lane = threadIdx.x & 31;
    const float* p = spk + (size_t)row * FDIM;
    uint32_t myword = 0;
    #pragma unroll
    for (int it = 0; it < 16; it++) {
        float x = p[it * 32 + lane];
        uint32_t b = __ballot_sync(0xFFFFFFFFu, x != 0.0f);
        if (lane == it) myword = b;
    }
    if (lane < 16) g_Sbit[(size_t)row * 16 + lane] = myword;
}

// ---------------------------------------------------------------------------
// Kernel 3: fp16 HMMA GEMM for one m-chunk (R12-verified core, m offset).
// ---------------------------------------------------------------------------
__global__ void __launch_bounds__(256, 2)
gemm_kernel(int m_off) {
    extern __shared__ char smem[];
    const uint32_t sb = smem_u32(smem);
    const int tid = threadIdx.x;
    const int l = tid & 31, wid = tid >> 5;
    const int wm = wid & 3, wn = wid >> 2;          // 4 m-warps x 2 n-warps
    const int n0 = blockIdx.x * NT;
    const size_t m0 = (size_t)m_off + (size_t)blockIdx.y * MT;

    float acc[2][8][4];                              // [mt][nt][frag] = 64 regs
    #pragma unroll
    for (int mt = 0; mt < 2; mt++)
        #pragma unroll
        for (int nt = 0; nt < 8; nt++)
            #pragma unroll
            for (int j = 0; j < 4; j++) acc[mt][nt][j] = 0.0f;

    // ---- A bits: whole 128-row x 512-bit strip, one group ----
    {
        #pragma unroll
        for (int q = 0; q < 2; q++) {                // 512 cp16
            int u = q * 256 + tid;
            int row = u >> 2, seg = u & 3;
            cp16(sb + row * ABIT_STRIDE + seg * 16,
                 g_Sbit + (m0 + row) * 16 + seg * 4);
        }
        asm volatile("cp.async.commit_group;" ::: "memory");
    }
    // ---- B loader: 2 planes x 128 rows x 128 B fp16, swizzled ----
    auto load_B = [&](int c, int stg) {
        const uint32_t base = sb + ABIT_SZ + stg * B_STG;
        #pragma unroll
        for (int q = 0; q < 8; q++) {                // 2048 cp16
            int u = q * 256 + tid;
            int pl = u >> 10, rem = u & 1023;
            int row = rem >> 3, seg = rem & 7;
            cp16(base + pl * (NT * 128) + row * 128
                      + ((seg * 16) ^ ((row & 7) << 4)),
                 g_Wp + (size_t)pl * (FDIM * FDIM)
                      + (size_t)(n0 + row) * FDIM + c * KC + seg * 8);
        }
        asm volatile("cp.async.commit_group;" ::: "memory");
    };

    load_B(0, 0);
    load_B(1, 1);

    // per-lane address components
    const int lq = l >> 2;                            // lane quarter 0..7
    const int sh0 = 2 * (l & 3);                      // bit offset in 16-col blk
    const int qB = l >> 3;
    const int rBl = ((qB >> 1) << 3) + (l & 7);       // B row within 16-pair
    const int cB = (qB & 1) * 16;
    const uint32_t bswz = ((uint32_t)(rBl & 7)) << 4;
    const uint32_t abit0 = sb + (uint32_t)((wm * 32 + lq) * ABIT_STRIDE);

    #pragma unroll 1
    for (int c = 0; c < NCHUNK; c++) {
        if (c < NCHUNK - 1) asm volatile("cp.async.wait_group 1;" ::: "memory");
        else                asm volatile("cp.async.wait_group 0;" ::: "memory");
        __syncthreads();

        // Load this chunk's 64 bits for each of the lane's 4 rows.
        uint32_t w0[2][2], w1[2][2];                 // [mt][half] -> lo/hi word
        #pragma unroll
        for (int mt = 0; mt < 2; mt++)
            #pragma unroll
            for (int h = 0; h < 2; h++) {
                uint32_t ad = abit0 + (uint32_t)((mt * 16 + h * 8) * ABIT_STRIDE
                                                 + c * 8);
                asm volatile("ld.shared.v2.b32 {%0,%1}, [%2];"
                             : "=r"(w0[mt][h]), "=r"(w1[mt][h]) : "r"(ad));
            }

        const uint32_t bbase = sb + ABIT_SZ + (c & 1) * B_STG;

        #pragma unroll
        for (int ks = 0; ks < 4; ks++) {
            const int shift = (ks & 1) * 16 + sh0;
            uint32_t a[2][4];
            #pragma unroll
            for (int mt = 0; mt < 2; mt++) {
                uint32_t vlo0 = ((ks < 2 ? w0[mt][0] : w1[mt][0]) >> shift) & 0x303u;
                uint32_t vlo1 = ((ks < 2 ? w0[mt][1] : w1[mt][1]) >> shift) & 0x303u;
                a[mt][0] = expand2(vlo0 & 3u);        // row r,   cols c,c+1
                a[mt][1] = expand2(vlo1 & 3u);        // row r+8, cols c,c+1
                a[mt][2] = expand2((vlo0 >> 8) & 3u); // row r,   cols c+8,c+9
                a[mt][3] = expand2((vlo1 >> 8) & 3u); // row r+8, cols c+8,c+9
            }
            #pragma unroll
            for (int pl = 0; pl < NPLANE; pl++) {
                #pragma unroll
                for (int p2 = 0; p2 < 4; p2++) {     // 2 n-tiles per ldmatrix
                    uint32_t bd = bbase + pl * (NT * 128)
                                + (wn * 64 + p2 * 16 + rBl) * 128
                                + (((uint32_t)(ks * 32 + cB)) ^ bswz);
                    uint32_t b0, b1, b2, b3;
                    LDSM4(b0, b1, b2, b3, bd);
                    #pragma unroll
                    for (int mt = 0; mt < 2; mt++) {
                        HMMA(acc[mt][2 * p2],     a[mt], b0, b1);
                        HMMA(acc[mt][2 * p2 + 1], a[mt], b2, b3);
                    }
                }
            }
        }

        __syncthreads();                 // B stage (c&1) consumed
        if (c + 2 < NCHUNK) load_B(c + 2, c & 1);
    }

    // ---- epilogue: direct coalesced float2 stores ----
    #pragma unroll
    for (int mt = 0; mt < 2; mt++)
        #pragma unroll
        for (int nt = 0; nt < 8; nt++) {
            const size_t row = m0 + wm * 32 + mt * 16 + (l >> 2);
            const int    col = n0 + wn * 64 + nt * 8 + (l & 3) * 2;
            *(float2*)(g_xs + row * FDIM + col) =
                make_float2(acc[mt][nt][0], acc[mt][nt][1]);
            *(float2*)(g_xs + (row + 8) * FDIM + col) =
                make_float2(acc[mt][nt][2], acc[mt][nt][3]);
        }
}

// ---------------------------------------------------------------------------
// Kernel 4: LIF scan. Thread = one neuron (b,f); xs[t][bf] coalesced.
// fp32-exact in reference op order; 16-deep load batch, streaming loads.
// ---------------------------------------------------------------------------
__global__ void __launch_bounds__(256)
scan_kernel(float* __restrict__ out) {
    const int bf = blockIdx.x * 256 + threadIdx.x;
    const float* p = g_xs + bf;
    float v = 0.0f, i = 0.0f, z = 0.0f;

    for (int t = 0; t < T_STEPS; t += 16) {
        float x[16];
        #pragma unroll
        for (int u = 0; u < 16; u++)
            x[u] = __ldcs(p + (size_t)(t + u) * BF);
        #pragma unroll
        for (int u = 0; u < 16; u++) {
            float vd = __fadd_rn(v, __fmul_rn(0.1f, __fadd_rn(-v, i)));
            float id = __fadd_rn(i, -__fmul_rn(0.2f, i));
            bool s = vd > 1.0f;
            z = s ? 1.0f : 0.0f;
            v = s ? 0.0f : vd;
            i = __fadd_rn(id, x[u]);
        }
    }
    out[bf]          = z;
    out[BF + bf]     = v;
    out[2 * BF + bf] = i;
}

// ---------------------------------------------------------------------------
// Host: pack chunks on the origin stream; gemm chunks fork onto two side
// streams (alternating, so consecutive chunks overlap tails) gated by pack
// events; scan joins after all gemm events. Event-fork pattern verified
// graph-capturable in R13.
// ---------------------------------------------------------------------------
extern "C" void kernel_launch(void* const* d_in, const int* in_sizes, int n_in,
                              void* d_out, int out_size) {
    const float* spikes = (const float*)d_in[0];  // [T, B, F] fp32 (binary)
    const float* W      = (const float*)d_in[1];  // [F, F] fp32
    float* out          = (float*)d_out;          // [3, B, F] fp32
    (void)in_sizes; (void)n_in; (void)out_size;

    static bool inited = false;
    static cudaStream_t sg[2];
    static cudaEvent_t evP[NPIPE], evG[NPIPE];
    if (!inited) {
        cudaStreamCreateWithFlags(&sg[0], cudaStreamNonBlocking);
        cudaStreamCreateWithFlags(&sg[1], cudaStreamNonBlocking);
        for (int k = 0; k < NPIPE; k++) {
            cudaEventCreateWithFlags(&evP[k], cudaEventDisableTiming);
            cudaEventCreateWithFlags(&evG[k], cudaEventDisableTiming);
        }
        cudaFuncSetAttribute(gemm_kernel,
                             cudaFuncAttributeMaxDynamicSharedMemorySize,
                             SMEM_TOTAL);
        inited = true;
    }

    wsplit_kernel<<<(FDIM * FDIM) / 256, 256>>>(W);

    for (int k = 0; k < NPIPE; k++) {
        pack_kernel<<<MCHUNK / 8, 256>>>(spikes, k * MCHUNK);
        cudaEventRecord(evP[k], 0);          // after wsplit+pack_k on stream 0
        cudaStream_t s = sg[k & 1];
        cudaStreamWaitEvent(s, evP[k], 0);
        gemm_kernel<<<dim3(FDIM / NT, MCHUNK / MT), 256, SMEM_TOTAL, s>>>(
            k * MCHUNK);
        cudaEventRecord(evG[k], s);
    }
    for (int k = 0; k < NPIPE; k++)
        cudaStreamWaitEvent(0, evG[k], 0);   // join fork
    scan_kernel<<<BF / 256, 256>>>(out);
}